// round 12
// baseline (speedup 1.0000x reference)
#include <cuda_runtime.h>
#include <cuda_fp16.h>
#include <stdint.h>

#define BATCH 16
#define SEQ   2048
#define DIM   128
#define BQ    128
#define BK    64
#define NT    256
#define KTILES (SEQ / BK)   // 32

// smem: 4 stages x [K16 16KB | V16 16KB] = 128KB, then P: 4 pairs x 4KB x 2 bufs = 32KB
#define STAGE_B    32768u
#define PBUF_OFF   131072u
#define SMEM_BYTES 163840u

__device__ uint2 g_K16[BATCH * SEQ * DIM / 4];
__device__ uint2 g_V16[BATCH * SEQ * DIM / 4];
__device__ float g_meanV[BATCH][DIM];
__device__ float g_part[64][BATCH][DIM];

// ---------------------------------------------------------------------------
// helpers
// ---------------------------------------------------------------------------
__device__ __forceinline__ float ex2(float x) {
    float y;
    asm("ex2.approx.f32 %0, %1;" : "=f"(y) : "f"(x));
    return y;
}
__device__ __forceinline__ uint32_t smem_u32(const void* p) {
    uint32_t a;
    asm("{ .reg .u64 t; cvta.to.shared.u64 t, %1; cvt.u32.u64 %0, t; }" : "=r"(a) : "l"(p));
    return a;
}
__device__ __forceinline__ void cp16(uint32_t dst, const void* src) {
    asm volatile("cp.async.cg.shared.global [%0], [%1], 16;" :: "r"(dst), "l"(src));
}
__device__ __forceinline__ uint32_t pkh(float lo, float hi) {
    uint32_t r;
    asm("cvt.rn.f16x2.f32 %0, %1, %2;" : "=r"(r) : "f"(hi), "f"(lo));
    return r;
}
__device__ __forceinline__ void mma16(float* c, const uint32_t* a, uint32_t b0, uint32_t b1) {
    asm volatile(
        "mma.sync.aligned.m16n8k16.row.col.f32.f16.f16.f32 "
        "{%0,%1,%2,%3}, {%4,%5,%6,%7}, {%8,%9}, {%0,%1,%2,%3};"
        : "+f"(c[0]), "+f"(c[1]), "+f"(c[2]), "+f"(c[3])
        : "r"(a[0]), "r"(a[1]), "r"(a[2]), "r"(a[3]), "r"(b0), "r"(b1));
}
__device__ __forceinline__ void ldsm4(uint32_t* r, uint32_t a) {
    asm volatile("ldmatrix.sync.aligned.m8n8.x4.shared.b16 {%0,%1,%2,%3}, [%4];"
        : "=r"(r[0]), "=r"(r[1]), "=r"(r[2]), "=r"(r[3]) : "r"(a));
}
__device__ __forceinline__ void ldsm4t(uint32_t* r, uint32_t a) {
    asm volatile("ldmatrix.sync.aligned.m8n8.x4.trans.shared.b16 {%0,%1,%2,%3}, [%4];"
        : "=r"(r[0]), "=r"(r[1]), "=r"(r[2]), "=r"(r[3]) : "r"(a));
}

// ---------------------------------------------------------------------------
// cvt_kernel: K,V fp32 -> fp16 with 16B stores + V column-sum partials.
// 1024 CTAs (b = blk>>6, 32-row slices). Thread owns 8 consecutive floats/iter;
// d-range fixed per thread: (tid%16)*8.
// ---------------------------------------------------------------------------
__global__ void cvt_kernel(const float* __restrict__ K, const float* __restrict__ V) {
    __shared__ float red[NT * 8];
    const int tid = threadIdx.x;
    const int b   = blockIdx.x >> 6;
    const int sl  = blockIdx.x & 63;
    const size_t fbase = ((size_t)b * SEQ + (size_t)sl * 32) * DIM;
    const float4* k4 = (const float4*)(K + fbase);
    const float4* v4 = (const float4*)(V + fbase);
    uint4* ko = (uint4*)(g_K16 + fbase / 4);
    uint4* vo = (uint4*)(g_V16 + fbase / 4);

    float4 ka[4], va[4];
    #pragma unroll
    for (int i = 0; i < 2; ++i) {
        int t8 = i * NT + tid;
        ka[2*i]   = k4[t8 * 2];
        ka[2*i+1] = k4[t8 * 2 + 1];
        va[2*i]   = v4[t8 * 2];
        va[2*i+1] = v4[t8 * 2 + 1];
    }
    float vs[8];
    #pragma unroll
    for (int j = 0; j < 8; ++j) vs[j] = 0.f;
    #pragma unroll
    for (int i = 0; i < 2; ++i) {
        int t8 = i * NT + tid;
        ko[t8] = make_uint4(pkh(ka[2*i].x, ka[2*i].y),   pkh(ka[2*i].z, ka[2*i].w),
                            pkh(ka[2*i+1].x, ka[2*i+1].y), pkh(ka[2*i+1].z, ka[2*i+1].w));
        vo[t8] = make_uint4(pkh(va[2*i].x, va[2*i].y),   pkh(va[2*i].z, va[2*i].w),
                            pkh(va[2*i+1].x, va[2*i+1].y), pkh(va[2*i+1].z, va[2*i+1].w));
        vs[0] += va[2*i].x; vs[1] += va[2*i].y; vs[2] += va[2*i].z; vs[3] += va[2*i].w;
        vs[4] += va[2*i+1].x; vs[5] += va[2*i+1].y; vs[6] += va[2*i+1].z; vs[7] += va[2*i+1].w;
    }
    #pragma unroll
    for (int j = 0; j < 8; ++j) red[tid * 8 + j] = vs[j];
    __syncthreads();
    if (tid < 16) {
        float s[8];
        #pragma unroll
        for (int j = 0; j < 8; ++j) s[j] = 0.f;
        #pragma unroll
        for (int g = 0; g < 16; ++g)
            #pragma unroll
            for (int j = 0; j < 8; ++j) s[j] += red[(g * 16 + tid) * 8 + j];
        #pragma unroll
        for (int j = 0; j < 8; ++j) g_part[sl][b][tid * 8 + j] = s[j];
    }
}

__global__ void meanv_final() {
    int b = blockIdx.x;
    int d = threadIdx.x;
    float s = 0.f;
    #pragma unroll
    for (int i = 0; i < 64; ++i) s += g_part[i][b][d];
    g_meanV[b][d] = s * (1.0f / SEQ);
}

// ---------------------------------------------------------------------------
// Flash attention, pair-split decomposition:
//  pair p = w>>1 owns q-rows [q0+32p, +32); h = w&1.
//  S phase : warp computes its 32 rows x keys [32h, 32h+32) of the tile.
//  P tile (32x64 fp16, swizzled) exchanged within pair via smem + bar.sync.
//  PV phase: warp computes its 32 rows x d-half [64h, +64) over ALL 64 keys.
//  l partials (key-halves) merged once at the end. O halves disjoint in D.
// ---------------------------------------------------------------------------
__global__ __launch_bounds__(NT, 1)
void attn_kernel(const float* __restrict__ Qg, const int* __restrict__ vlg,
                 float* __restrict__ Og)
{
    extern __shared__ char smem[];

    const int tid  = threadIdx.x;
    const int lane = tid & 31;
    const int w    = tid >> 5;
    const int p    = w >> 1;
    const int h    = w & 1;
    const int qr   = lane >> 2;
    const int qc   = lane & 3;
    const int b    = blockIdx.y;
    const int q0   = blockIdx.x * BQ;
    const int vl   = vlg[b];

    // ---- fully-masked tile ----
    if (q0 >= vl) {
        int row = tid >> 1, hh = tid & 1;
        const float4* mv = (const float4*)&g_meanV[b][hh * 64];
        float4* o4 = (float4*)(Og + ((size_t)b * SEQ + q0 + row) * DIM + hh * 64);
        #pragma unroll
        for (int j = 0; j < 16; ++j) o4[j] = mv[j];
        return;
    }

    const uint32_t sbase = smem_u32(smem);
    const uint8_t* kb16 = (const uint8_t*)g_K16 + (size_t)b * SEQ * DIM * 2;
    const uint8_t* vb16 = (const uint8_t*)g_V16 + (size_t)b * SEQ * DIM * 2;

    // cp.async pattern (16B chunks): r = i*16 + (tid>>4), c = tid&15
    const uint32_t csrc = (uint32_t)(tid & 15) * 16u;
    const uint32_t r0t  = (uint32_t)(tid >> 4);
    const uint32_t swz  = (uint32_t)((tid & 15) ^ (int)(r0t & 7)) << 4;

    #pragma unroll
    for (int t = 0; t < 3; ++t) {
        const uint8_t* ks = kb16 + (size_t)t * 16384;
        const uint8_t* vs = vb16 + (size_t)t * 16384;
        uint32_t stg = (uint32_t)t * STAGE_B;
        #pragma unroll
        for (int i = 0; i < 4; ++i) {
            uint32_t r = (uint32_t)i * 16u + r0t;
            cp16(sbase + stg + r * 256u + swz, ks + r * 256u + csrc);
            cp16(sbase + stg + 16384u + r * 256u + swz, vs + r * 256u + csrc);
        }
        asm volatile("cp.async.commit_group;");
    }

    // ---- Q A-frags for 32 rows (2 m-blocks), fp16, scaled ----
    const float qscale = 0.088388347648318447f * 1.4426950408889634f;
    uint32_t qa[2][8][4];
    #pragma unroll
    for (int mb = 0; mb < 2; ++mb) {
        const float* r0 = Qg + ((size_t)b * SEQ + q0 + p * 32 + mb * 16 + qr) * DIM;
        const float* r1 = r0 + 8 * DIM;
        #pragma unroll
        for (int kb = 0; kb < 8; ++kb) {
            int d0 = kb * 16 + 2 * qc;
            float2 a = *(const float2*)(r0 + d0);
            float2 c = *(const float2*)(r1 + d0);
            float2 e = *(const float2*)(r0 + d0 + 8);
            float2 f = *(const float2*)(r1 + d0 + 8);
            qa[mb][kb][0] = pkh(a.x * qscale, a.y * qscale);
            qa[mb][kb][1] = pkh(c.x * qscale, c.y * qscale);
            qa[mb][kb][2] = pkh(e.x * qscale, e.y * qscale);
            qa[mb][kb][3] = pkh(f.x * qscale, f.y * qscale);
        }
    }

    float o[2][8][4];
    #pragma unroll
    for (int mb = 0; mb < 2; ++mb)
        #pragma unroll
        for (int j = 0; j < 8; ++j) { o[mb][j][0] = o[mb][j][1] = o[mb][j][2] = o[mb][j][3] = 0.f; }
    float lr[2][2] = {{0.f, 0.f}, {0.f, 0.f}};

    const uint32_t r7 = (uint32_t)(lane & 7);
    const int      lt = lane >> 3;
    const uint32_t kL = sbase + r7 * 256u + (uint32_t)(32 * h) * 256u;     // S: this warp's key-half
    const uint32_t vL = sbase + 16384u + (uint32_t)(8 * (lt & 1)) * 256u + r7 * 256u;
    const uint32_t Pp = sbase + PBUF_OFF + (uint32_t)p * 4096u;            // pair's P buffer (x2)
    char* Ppc = smem + PBUF_OFF + p * 4096;

    for (int kt = 0; kt < KTILES; ++kt) {
        asm volatile("cp.async.wait_group 2;");
        __syncthreads();

        if (kt + 3 < KTILES) {
            const uint32_t nb = (uint32_t)((kt + 3) & 3) * STAGE_B;
            const uint8_t* ks = kb16 + (size_t)(kt + 3) * 16384;
            const uint8_t* vs = vb16 + (size_t)(kt + 3) * 16384;
            #pragma unroll
            for (int i = 0; i < 4; ++i) {
                uint32_t r = (uint32_t)i * 16u + r0t;
                cp16(sbase + nb + r * 256u + swz, ks + r * 256u + csrc);
                cp16(sbase + nb + 16384u + r * 256u + swz, vs + r * 256u + csrc);
            }
        }
        asm volatile("cp.async.commit_group;");

        const uint32_t stg  = (uint32_t)(kt & 3) * STAGE_B;
        const uint32_t poff = (uint32_t)(kt & 1) * 16384u;

        // ---- S: 32 rows x 32 keys (this warp's half) ----
        float sacc[2][4][4];
        #pragma unroll
        for (int mb = 0; mb < 2; ++mb)
            #pragma unroll
            for (int n = 0; n < 4; ++n) { sacc[mb][n][0] = sacc[mb][n][1] = sacc[mb][n][2] = sacc[mb][n][3] = 0.f; }

        #pragma unroll
        for (int nb = 0; nb < 4; ++nb) {
            uint32_t abase = kL + stg + (uint32_t)(nb * 8) * 256u;
            #pragma unroll
            for (int g = 0; g < 4; ++g) {
                uint32_t r[4];
                ldsm4(r, abase + ((((uint32_t)(4 * g + lt)) ^ r7) << 4));
                #pragma unroll
                for (int mb = 0; mb < 2; ++mb) {
                    mma16(sacc[mb][nb], qa[mb][2 * g],     r[0], r[1]);
                    mma16(sacc[mb][nb], qa[mb][2 * g + 1], r[2], r[3]);
                }
            }
        }

        // ---- softmax + P -> pair smem (rows 32, keys 64 fp16, chunk^(row&7) swizzle) ----
        #pragma unroll
        for (int mb = 0; mb < 2; ++mb) {
            #pragma unroll
            for (int nb = 0; nb < 4; ++nb) {
                float e0 = ex2(sacc[mb][nb][0]);
                float e1 = ex2(sacc[mb][nb][1]);
                float e2 = ex2(sacc[mb][nb][2]);
                float e3 = ex2(sacc[mb][nb][3]);
                lr[mb][0] += e0 + e1;
                lr[mb][1] += e2 + e3;
                uint32_t chunk = (uint32_t)((4 * h + nb) ^ qr) << 4;
                int row = mb * 16 + qr;
                *(uint32_t*)(Ppc + poff + row * 128 + chunk + 4 * qc)       = pkh(e0, e1);
                *(uint32_t*)(Ppc + poff + (row + 8) * 128 + chunk + 4 * qc) = pkh(e2, e3);
            }
        }
        asm volatile("bar.sync %0, 64;" :: "r"(p + 1) : "memory");

        // ---- load full P as A-frags (2 mb x 4 kb) ----
        uint32_t pa[2][4][4];
        {
            uint32_t prow = (uint32_t)((lt & 1) * 8) + r7;
            #pragma unroll
            for (int mb = 0; mb < 2; ++mb) {
                uint32_t rbase = Pp + poff + ((uint32_t)(mb * 16) + prow) * 128u;
                #pragma unroll
                for (int kb = 0; kb < 4; ++kb) {
                    ldsm4(pa[mb][kb], rbase + ((((uint32_t)(2 * kb + (lt >> 1))) ^ r7) << 4));
                }
            }
        }

        // ---- PV: 32 rows x d-half [64h,+64) over all 64 keys ----
        #pragma unroll
        for (int np = 0; np < 4; ++np) {
            uint32_t coff = (((uint32_t)(8 * h + 2 * np + (lt >> 1))) ^ r7) << 4;
            #pragma unroll
            for (int kb = 0; kb < 4; ++kb) {
                uint32_t r[4];
                ldsm4t(r, vL + stg + (uint32_t)kb * 4096u + coff);
                #pragma unroll
                for (int mb = 0; mb < 2; ++mb) {
                    mma16(o[mb][2 * np],     pa[mb][kb], r[0], r[1]);
                    mma16(o[mb][2 * np + 1], pa[mb][kb], r[2], r[3]);
                }
            }
        }
    }

    // ---- merge row-sum halves across the pair ----
    #pragma unroll
    for (int mb = 0; mb < 2; ++mb) {
        lr[mb][0] += __shfl_xor_sync(0xffffffffu, lr[mb][0], 1);
        lr[mb][0] += __shfl_xor_sync(0xffffffffu, lr[mb][0], 2);
        lr[mb][1] += __shfl_xor_sync(0xffffffffu, lr[mb][1], 1);
        lr[mb][1] += __shfl_xor_sync(0xffffffffu, lr[mb][1], 2);
    }
    float* lsm = (float*)smem;       // stage 0 region, free by now
    __syncthreads();
    if (qc == 0) {
        #pragma unroll
        for (int mb = 0; mb < 2; ++mb) {
            lsm[w * 32 + mb * 16 + qr]     = lr[mb][0];
            lsm[w * 32 + mb * 16 + qr + 8] = lr[mb][1];
        }
    }
    __syncthreads();

    // ---- epilogue: warp writes its 32 rows x d-half ----
    #pragma unroll
    for (int mb = 0; mb < 2; ++mb) {
        const int row0 = q0 + p * 32 + mb * 16 + qr;
        const int row1 = row0 + 8;
        float inv0 = 1.0f / (lr[mb][0] + lsm[(w ^ 1) * 32 + mb * 16 + qr]);
        float inv1 = 1.0f / (lr[mb][1] + lsm[(w ^ 1) * 32 + mb * 16 + qr + 8]);
        float* O0 = Og + ((size_t)b * SEQ + row0) * DIM + h * 64;
        float* O1 = Og + ((size_t)b * SEQ + row1) * DIM + h * 64;
        const bool m0 = row0 >= vl;
        const bool m1 = row1 >= vl;
        #pragma unroll
        for (int j = 0; j < 8; ++j) {
            int col = j * 8 + 2 * qc;
            float2 a0 = m0 ? *(const float2*)&g_meanV[b][h * 64 + col]
                           : make_float2(o[mb][j][0] * inv0, o[mb][j][1] * inv0);
            float2 a1 = m1 ? *(const float2*)&g_meanV[b][h * 64 + col]
                           : make_float2(o[mb][j][2] * inv1, o[mb][j][3] * inv1);
            *(float2*)(O0 + col) = a0;
            *(float2*)(O1 + col) = a1;
        }
    }
}

extern "C" void kernel_launch(void* const* d_in, const int* in_sizes, int n_in,
                              void* d_out, int out_size) {
    const float* Q  = (const float*)d_in[0];
    const float* K  = (const float*)d_in[1];
    const float* V  = (const float*)d_in[2];
    const int*   vl = (const int*)d_in[3];
    float* out = (float*)d_out;

    cvt_kernel<<<BATCH * 64, NT>>>(K, V);
    meanv_final<<<BATCH, DIM>>>();

    cudaFuncSetAttribute(attn_kernel, cudaFuncAttributeMaxDynamicSharedMemorySize, SMEM_BYTES);
    dim3 grid(SEQ / BQ, BATCH);
    attn_kernel<<<grid, NT, SMEM_BYTES>>>(Q, vl, out);
}